// round 16
// baseline (speedup 1.0000x reference)
#include <cuda_runtime.h>
#include <cuda_fp16.h>
#include <cstdint>
#include <math.h>

#define BATCH 4
#define CH    128
#define C8    16
#define NSP   4096
#define CO    160
#define TI    64
#define TJ    64
#define NTJ   (NSP / TJ)
#define NSPLIT 4
#define NTJC  (NTJ / NSPLIT)   // 16 key-tiles per CTA

// f16 operands produced by proj kernel
__device__ __align__(16) __half g_q2[BATCH * NSP * 32];  // [b][n][ qh(16) | ql(16) ]
__device__ __align__(16) __half g_k2[BATCH * NSP * 32];  // [b][n][ kh(16) | kl(16) ]
__device__ __align__(16) __half g_v [BATCH * CH * NSP];  // [b][c][n] single f16

// W in f16 hi/lo + bias (filled by wconv_kernel each call)
__device__ __align__(16) __half g_Wh[CO * CH];   // [o][c]
__device__ __align__(16) __half g_Wl[CO * CH];
__device__ float g_bias[CO];

// split-K partials: per-split NORMALIZED O in f16, plus m/l in f32
__device__ __align__(16) __half g_po[NSPLIT * BATCH * CH * NSP];
__device__ float g_m[NSPLIT * BATCH * NSP];
__device__ float g_l[NSPLIT * BATCH * NSP];

extern __shared__ __align__(16) char dsmem[];

// ---------------------------------------------------------------------------
// helpers
// ---------------------------------------------------------------------------
__device__ __forceinline__ uint32_t smem_u32(const void* p) {
    uint32_t a;
    asm("{ .reg .u64 t; cvta.to.shared.u64 t, %1; cvt.u32.u64 %0, t; }"
        : "=r"(a) : "l"(p));
    return a;
}

#define LDSM4(r, addr) \
    asm volatile("ldmatrix.sync.aligned.m8n8.x4.shared.b16 {%0,%1,%2,%3}, [%4];" \
        : "=r"((r)[0]), "=r"((r)[1]), "=r"((r)[2]), "=r"((r)[3]) : "r"(addr))
#define LDSM4T(r, addr) \
    asm volatile("ldmatrix.sync.aligned.m8n8.x4.trans.shared.b16 {%0,%1,%2,%3}, [%4];" \
        : "=r"((r)[0]), "=r"((r)[1]), "=r"((r)[2]), "=r"((r)[3]) : "r"(addr))

// D(+=) = A(m16k16 f16) * B(k16n8 f16), f32 accum
#define MMAH(d, a, b) \
    asm volatile("mma.sync.aligned.m16n8k16.row.col.f32.f16.f16.f32 " \
        "{%0,%1,%2,%3}, {%4,%5,%6,%7}, {%8,%9}, {%0,%1,%2,%3};" \
        : "+f"((d)[0]), "+f"((d)[1]), "+f"((d)[2]), "+f"((d)[3]) \
        : "r"((a)[0]), "r"((a)[1]), "r"((a)[2]), "r"((a)[3]), \
          "r"((b)[0]), "r"((b)[1]))

#define CP16(dst, src) \
    asm volatile("cp.async.cg.shared.global [%0], [%1], 16;" :: "r"(dst), "l"(src))
#define CPCOMMIT() asm volatile("cp.async.commit_group;" ::: "memory")
#define CPWAIT0()  asm volatile("cp.async.wait_group 0;" ::: "memory")

#define LOG2E 1.4426950408889634f

// 2^t on the SFU pipe (MUFU.EX2)
__device__ __forceinline__ float fex2(float t) {
    float r;
    asm("ex2.approx.f32 %0, %1;" : "=f"(r) : "f"(t));
    return r;
}

__device__ __forceinline__ uint32_t packh2(float lo, float hi) {
    __half2 h = __floats2half2_rn(lo, hi);  // lo -> low 16 bits
    return *reinterpret_cast<uint32_t*>(&h);
}

// ---------------------------------------------------------------------------
// W conversion: f32 -> f16 hi/lo + bias gather. Tiny, runs once per call.
// ---------------------------------------------------------------------------
__global__ __launch_bounds__(256) void wconv_kernel(
    const float* __restrict__ Wq, const float* __restrict__ bq,
    const float* __restrict__ Wk, const float* __restrict__ bk,
    const float* __restrict__ Wv, const float* __restrict__ bv)
{
    int t = blockIdx.x * 256 + threadIdx.x;
    if (t < CO * CH) {
        int o = t >> 7, c = t & 127;
        float w;
        if (o < 16)       w = Wq[o * CH + c];
        else if (o < 32)  w = Wk[(o - 16) * CH + c];
        else              w = Wv[(o - 32) * CH + c];
        __half h = __float2half_rn(w);
        g_Wh[t] = h;
        g_Wl[t] = __float2half_rn(w - __half2float(h));
    }
    if (t < CO)
        g_bias[t] = (t < 16) ? bq[t] : (t < 32) ? bk[t - 16] : bv[t - 32];
}

// ---------------------------------------------------------------------------
// HMMA projection: O^T(n,160) = x^T(n,128) @ W^T(128,160) + b, f16 hi/lo.
// z-split over 2 o-halves (80 rows each) -> smem 113.2 KB -> 2 CTAs/SM.
// Block = (128-n tile, batch, o-half), 256 threads. Grid (32,4,2) = one wave.
// ---------------------------------------------------------------------------
// smem byte offsets: x pitch 272B (136 f16), W pitch 272B (80 rows per half)
#define PJ_XH 0
#define PJ_XL 34816
#define PJ_WH 69632
#define PJ_WL 91392
#define SMEM_PROJ 113152

__global__ __launch_bounds__(256, 2) void proj_kernel(const float* __restrict__ x)
{
    const uint32_t sb = smem_u32(dsmem);
    const int t    = threadIdx.x;
    const int lane = t & 31;
    const int w    = t >> 5;
    const int b    = blockIdx.y;
    const int pass = blockIdx.z;       // o-half: rows [pass*80, pass*80+80)
    const int n0   = blockIdx.x * 128;

    // cp.async W hi/lo: 80 rows x 256 B -> pitch 272 B
    {
        const char* wh = (const char*)(g_Wh + (size_t)pass * 80 * CH);
        const char* wl = (const char*)(g_Wl + (size_t)pass * 80 * CH);
        #pragma unroll
        for (int u = 0; u < 5; ++u) {
            int m = t + u * 256;
            int r = m >> 4, ch = m & 15;
            CP16(sb + PJ_WH + (uint32_t)r * 272 + ch * 16,
                 wh + (size_t)r * 256 + ch * 16);
            CP16(sb + PJ_WL + (uint32_t)r * 272 + ch * 16,
                 wl + (size_t)r * 256 + ch * 16);
        }
    }
    CPCOMMIT();

    // x tile: 128c x 128n f32 -> f16 hi/lo smem [c][n], pitch 272 B
    const float* xb = x + (size_t)(b * CH) * NSP + n0;
    #pragma unroll
    for (int u = 0; u < 16; ++u) {
        int m  = t + u * 256;
        int c  = m >> 5, nq = m & 31;
        float4 v = *(const float4*)(xb + (size_t)c * NSP + nq * 4);
        __half h0 = __float2half_rn(v.x), h1 = __float2half_rn(v.y);
        __half h2 = __float2half_rn(v.z), h3 = __float2half_rn(v.w);
        __half l0 = __float2half_rn(v.x - __half2float(h0));
        __half l1 = __float2half_rn(v.y - __half2float(h1));
        __half l2 = __float2half_rn(v.z - __half2float(h2));
        __half l3 = __float2half_rn(v.w - __half2float(h3));
        __half2* ph = (__half2*)(dsmem + PJ_XH + c * 272 + nq * 8);
        __half2* pl = (__half2*)(dsmem + PJ_XL + c * 272 + nq * 8);
        __half2 a; a.x = h0; a.y = h1;
        __half2 bb; bb.x = h2; bb.y = h3;
        ph[0] = a; ph[1] = bb;
        a.x = l0; a.y = l1; bb.x = l2; bb.y = l3;
        pl[0] = a; pl[1] = bb;
    }
    CPWAIT0();
    __syncthreads();

    // ldmatrix address components
    const int krow = (lane & 7) + ((lane >> 4) << 3);
    const int mcol = ((lane >> 3) & 1) * 8;

    float acc[10][4];
    #pragma unroll
    for (int a = 0; a < 10; ++a)
        #pragma unroll
        for (int d = 0; d < 4; ++d) acc[a][d] = 0.f;

    // O^T = xh@Wh + xl@Wh + xh@Wl ; kt outer so A-frags stay transient
    #pragma unroll
    for (int kt = 0; kt < 8; ++kt) {
        uint32_t Ah[4], Al[4];
        uint32_t aa = sb + PJ_XH + (uint32_t)(kt * 16 + krow) * 272
                      + (w * 16 + mcol) * 2;
        LDSM4T(Ah, aa);
        LDSM4T(Al, aa + (PJ_XL - PJ_XH));
        #pragma unroll
        for (int ot = 0; ot < 5; ++ot) {
            uint32_t Bh[4], Bl[4];
            uint32_t ba = sb + PJ_WH + (uint32_t)(ot * 16 + krow) * 272
                          + (kt * 16 + mcol) * 2;
            LDSM4(Bh, ba);
            LDSM4(Bl, ba + (PJ_WL - PJ_WH));
            MMAH(acc[2 * ot],     Ah, Bh);
            MMAH(acc[2 * ot + 1], Ah, Bh + 2);
            MMAH(acc[2 * ot],     Al, Bh);
            MMAH(acc[2 * ot + 1], Al, Bh + 2);
            MMAH(acc[2 * ot],     Ah, Bl);
            MMAH(acc[2 * ot + 1], Ah, Bl + 2);
        }
    }

    // Epilogue: bias add (from global), split outputs.
    const int gid = lane >> 2, m4 = lane & 3;
    const int na  = n0 + w * 16 + gid;

    #pragma unroll
    for (int ot = 0; ot < 5; ++ot) {
        #pragma unroll
        for (int h2 = 0; h2 < 2; ++h2) {
            const float* a = acc[2 * ot + h2];
            int o0 = pass * 80 + ot * 16 + h2 * 8 + 2 * m4;
            float bb0 = __ldg(&g_bias[o0]);
            float bb1 = __ldg(&g_bias[o0 + 1]);
            float v0 = a[0] + bb0, v1 = a[1] + bb1;
            float v2 = a[2] + bb0, v3 = a[3] + bb1;

            if (o0 < 32) {
                __half* dst = (o0 < 16) ? g_q2 : g_k2;
                int oc = (o0 < 16) ? o0 : (o0 - 16);
                size_t bA = ((size_t)b * NSP + na) * 32;
                size_t bB = ((size_t)b * NSP + na + 8) * 32;
                __half h;
                h = __float2half_rn(v0);
                dst[bA + oc]      = h;
                dst[bA + oc + 16] = __float2half_rn(v0 - __half2float(h));
                h = __float2half_rn(v1);
                dst[bA + oc + 1]  = h;
                dst[bA + oc + 17] = __float2half_rn(v1 - __half2float(h));
                h = __float2half_rn(v2);
                dst[bB + oc]      = h;
                dst[bB + oc + 16] = __float2half_rn(v2 - __half2float(h));
                h = __float2half_rn(v3);
                dst[bB + oc + 1]  = h;
                dst[bB + oc + 17] = __float2half_rn(v3 - __half2float(h));
            } else {
                int c = o0 - 32;
                size_t rb = ((size_t)b * CH + c) * NSP;
                g_v[rb + na]           = __float2half_rn(v0);
                g_v[rb + na + 8]       = __float2half_rn(v2);
                g_v[rb + NSP + na]     = __float2half_rn(v1);
                g_v[rb + NSP + na + 8] = __float2half_rn(v3);
            }
        }
    }
}

// ---------------------------------------------------------------------------
// HMMA flash attention, f16, online softmax, split-K over key tiles.
// 64-q CTA, 4 warps, 3 CTAs/SM; grid (64, 4, NSPLIT) = 1024 CTAs.
// Partials stored NORMALIZED in f16.
// ---------------------------------------------------------------------------
#define PI 68   // out staging pitch in f32

// smem byte offsets (per CTA: 52.7 KB -> 3 CTAs/SM)
#define OFF_Q    0
#define OFF_KS0  5120
#define OFF_V0   10240
#define OFF_KS1  28672
#define OFF_V1   33792
#define SMEM_ATTN (52224 + 512)

__device__ __forceinline__ void prefetch_tile(int b, int j0,
                                              uint32_t ks, uint32_t vs, int tid)
{
    // K: 64 rows x 64 B -> pitch 80 B
    {
        const char* kg = (const char*)(g_k2 + ((size_t)b * NSP + j0) * 32);
        #pragma unroll
        for (int u = 0; u < 2; ++u) {
            int m = tid + u * 128;
            int r = m >> 2, ch = m & 3;
            CP16(ks + (uint32_t)r * 80 + ch * 16, kg + (size_t)r * 64 + ch * 16);
        }
    }
    // V: 128 rows (c) x 128 B (64 f16 j) -> pitch 144 B
    const char* vg = (const char*)(g_v + (size_t)b * CH * NSP + j0);
    #pragma unroll
    for (int u = 0; u < 8; ++u) {
        int m = tid + u * 128;
        int r = m >> 3, ch = m & 7;
        CP16(vs + (uint32_t)r * 144 + ch * 16, vg + (size_t)r * (NSP * 2) + ch * 16);
    }
}

__global__ __launch_bounds__(128, 3) void attn_kernel()
{
    const uint32_t sb = smem_u32(dsmem);
    const int tid  = threadIdx.x;
    const int lane = tid & 31;
    const int wid  = tid >> 5;
    const int b    = blockIdx.y;
    const int h    = blockIdx.z;
    const int i0   = blockIdx.x * TI;
    const int iw   = wid * 16;
    const int gid  = lane >> 2;
    const int m4   = lane & 3;

    const uint32_t KS[2] = {sb + OFF_KS0, sb + OFF_KS1};
    const uint32_t VS[2] = {sb + OFF_V0,  sb + OFF_V1};
    float* outs = (float*)(dsmem + OFF_KS0);   // epilogue reuse

    // Load Q tile: 64 rows x 64 B -> pitch 80 B
    {
        const uint4* src = (const uint4*)(g_q2 + ((size_t)b * NSP + i0) * 32);
        #pragma unroll
        for (int u = 0; u < 2; ++u) {
            int m = tid + u * 128;
            int r = m >> 2, ch = m & 3;
            *(uint4*)(dsmem + OFF_Q + r * 80 + ch * 16) = src[m];
        }
    }
    prefetch_tile(b, h * NTJC * TJ, KS[0], VS[0], tid);
    CPCOMMIT();
    __syncthreads();

    // Resident A-fragments of Q (hi and lo)
    uint32_t qh[4], ql[4];
    {
        uint32_t a = sb + OFF_Q + (uint32_t)(iw + (lane & 15)) * 80 + (lane >> 4) * 16;
        LDSM4(qh, a);
        LDSM4(ql, a + 32);
    }

    // ldmatrix address components for B operands (non-trans)
    const int brow = (lane & 7) + ((lane >> 4) << 3);
    const int bcol = ((lane >> 3) & 1) * 8;

    float o[16][4];
    #pragma unroll
    for (int a = 0; a < 16; ++a)
        #pragma unroll
        for (int d = 0; d < 4; ++d) o[a][d] = 0.f;

    float lsum0 = 0.f, lsum1 = 0.f;
    float m0 = -60.f, m1 = -60.f;    // running row maxes (safe floor)

    for (int jt = 0; jt < NTJC; ++jt) {
        CPWAIT0();
        __syncthreads();
        if (jt + 1 < NTJC) {
            int ns = (jt + 1) & 1;
            prefetch_tile(b, (h * NTJC + jt + 1) * TJ, KS[ns], VS[ns], tid);
            CPCOMMIT();
        }
        const int st = jt & 1;

        // ---- QK: S(16i x 64j) = qh*kh + ql*kh + qh*kl  (kh frags reused)
        float sacc[8][4];
        #pragma unroll
        for (int a = 0; a < 8; ++a)
            #pragma unroll
            for (int d = 0; d < 4; ++d) sacc[a][d] = 0.f;

        #pragma unroll
        for (int np = 0; np < 4; ++np) {
            uint32_t base = KS[st] + (uint32_t)(16 * np + brow) * 80 + bcol * 2;
            uint32_t bKh[4], bKl[4];
            LDSM4(bKh, base);
            LDSM4(bKl, base + 32);
            MMAH(sacc[2 * np],     qh, bKh);
            MMAH(sacc[2 * np + 1], qh, bKh + 2);
            MMAH(sacc[2 * np],     ql, bKh);
            MMAH(sacc[2 * np + 1], ql, bKh + 2);
            MMAH(sacc[2 * np],     qh, bKl);
            MMAH(sacc[2 * np + 1], qh, bKl + 2);
        }

        // ---- online softmax: row max over this tile (rows live in lane quads)
        float tm0 = -1e30f, tm1 = -1e30f;
        #pragma unroll
        for (int a = 0; a < 8; ++a) {
            tm0 = fmaxf(tm0, fmaxf(sacc[a][0], sacc[a][1]));
            tm1 = fmaxf(tm1, fmaxf(sacc[a][2], sacc[a][3]));
        }
        tm0 = fmaxf(tm0, __shfl_xor_sync(0xFFFFFFFFu, tm0, 1));
        tm0 = fmaxf(tm0, __shfl_xor_sync(0xFFFFFFFFu, tm0, 2));
        tm1 = fmaxf(tm1, __shfl_xor_sync(0xFFFFFFFFu, tm1, 1));
        tm1 = fmaxf(tm1, __shfl_xor_sync(0xFFFFFFFFu, tm1, 2));

        const float mn0 = fmaxf(m0, tm0);
        const float mn1 = fmaxf(m1, tm1);
        const float sc0 = fex2((m0 - mn0) * LOG2E);
        const float sc1 = fex2((m1 - mn1) * LOG2E);
        m0 = mn0; m1 = mn1;
        lsum0 *= sc0;
        lsum1 *= sc1;
        // Rescale O only if some row max moved (rare after early tiles)
        if (__any_sync(0xFFFFFFFFu, (sc0 < 1.f) || (sc1 < 1.f))) {
            #pragma unroll
            for (int a = 0; a < 16; ++a) {
                o[a][0] *= sc0; o[a][1] *= sc0;
                o[a][2] *= sc1; o[a][3] *= sc1;
            }
        }

        // ---- p = exp(s - m) in (0,1] on the MUFU pipe; pack to f16 A-frags
        const float c0 = -mn0 * LOG2E;
        const float c1 = -mn1 * LOG2E;
        uint32_t ph[16];
        #pragma unroll
        for (int a = 0; a < 8; ++a) {
            float p0 = fex2(fmaf(sacc[a][0], LOG2E, c0));
            float p1 = fex2(fmaf(sacc[a][1], LOG2E, c0));
            float p2 = fex2(fmaf(sacc[a][2], LOG2E, c1));
            float p3 = fex2(fmaf(sacc[a][3], LOG2E, c1));
            lsum0 += p0 + p1;
            lsum1 += p2 + p3;
            ph[2 * a]     = packh2(p0, p1);
            ph[2 * a + 1] = packh2(p2, p3);
        }

        // ---- PV: O(16i x 128c) += P(f16) * V(f16)
        #pragma unroll
        for (int t4 = 0; t4 < 4; ++t4) {
            const uint32_t* A = &ph[4 * t4];
            #pragma unroll
            for (int p = 0; p < 8; ++p) {
                uint32_t bv[4];
                LDSM4(bv, VS[st] + (uint32_t)(16 * p + brow) * 144 + (16 * t4 + bcol) * 2);
                MMAH(o[2 * p],     A, bv);
                MMAH(o[2 * p + 1], A, bv + 2);
            }
        }
    }

    // ---- l reduction (4 lanes per row hold partials); write m/l partials
    lsum0 += __shfl_xor_sync(0xFFFFFFFFu, lsum0, 1);
    lsum0 += __shfl_xor_sync(0xFFFFFFFFu, lsum0, 2);
    lsum1 += __shfl_xor_sync(0xFFFFFFFFu, lsum1, 1);
    lsum1 += __shfl_xor_sync(0xFFFFFFFFu, lsum1, 2);
    if (m4 == 0) {
        size_t mb = ((size_t)h * BATCH + b) * NSP + i0 + iw;
        g_m[mb + gid]     = m0;
        g_m[mb + gid + 8] = m1;
        g_l[mb + gid]     = lsum0;
        g_l[mb + gid + 8] = lsum1;
    }
    __syncthreads();   // all PV reads of V/K smem complete before reuse

    // ---- stage per-split NORMALIZED O to smem [c][i]
    const float inv0 = 1.f / lsum0;
    const float inv1 = 1.f / lsum1;
    #pragma unroll
    for (int a = 0; a < 16; ++a) {
        int c = 8 * a + 2 * m4;
        outs[c * PI + iw + gid]           = o[a][0] * inv0;
        outs[(c + 1) * PI + iw + gid]     = o[a][1] * inv0;
        outs[c * PI + iw + gid + 8]       = o[a][2] * inv1;
        outs[(c + 1) * PI + iw + gid + 8] = o[a][3] * inv1;
    }
    __syncthreads();

    // ---- coalesced f16 partial-O store
    __half* pob = g_po + (((size_t)h * BATCH + b) * CH) * NSP + i0;
    for (int m = tid; m < CH * (TI / 4); m += 128) {
        int c = m >> 4, i4 = (m & 15) * 4;
        float4 ov = *(const float4*)(outs + c * PI + i4);
        uint2 hv;
        hv.x = packh2(ov.x, ov.y);
        hv.y = packh2(ov.z, ov.w);
        *(uint2*)(pob + (size_t)c * NSP + i4) = hv;
    }
}

// ---------------------------------------------------------------------------
// Combine: out = gamma * sum_h Ohat_h * (l_h a_h / sum l_h a_h) + x
// ---------------------------------------------------------------------------
__global__ __launch_bounds__(256) void combine_kernel(
    const float* __restrict__ x,
    const float* __restrict__ gamma,
    float* __restrict__ out)
{
    const int t  = threadIdx.x;
    const int b  = blockIdx.y;
    const int i  = blockIdx.x * 64 + (t & 63);
    const int cg = blockIdx.z * 4 + (t >> 6);   // 16 channel groups of 8

    const size_t nidx = (size_t)b * NSP + i;
    float mh[NSPLIT], lh[NSPLIT], ah[NSPLIT];
    float M = -1e30f;
    #pragma unroll
    for (int h = 0; h < NSPLIT; ++h) {
        mh[h] = g_m[(size_t)h * BATCH * NSP + nidx];
        lh[h] = g_l[(size_t)h * BATCH * NSP + nidx];
        M = fmaxf(M, mh[h]);
    }
    float denom = 0.f;
    #pragma unroll
    for (int h = 0; h < NSPLIT; ++h) {
        ah[h] = lh[h] * fex2((mh[h] - M) * LOG2E);
        denom += ah[h];
    }
    const float gs = gamma[0] / denom;
    #pragma unroll
    for (int h = 0; h < NSPLIT; ++h) ah[h] *= gs;

    #pragma unroll
    for (int cc = 0; cc < 8; ++cc) {
        int c = cg * 8 + cc;
        size_t off = ((size_t)b * CH + c) * NSP + i;
        float acc = x[off];
        #pragma unroll
        for (int h = 0; h < NSPLIT; ++h)
            acc = fmaf(__half2float(g_po[(size_t)h * BATCH * CH * NSP + off]),
                       ah[h], acc);
        out[off] = acc;
    }
}

// ---------------------------------------------------------------------------
extern "C" void kernel_launch(void* const* d_in, const int* in_sizes, int n_in,
                              void* d_out, int out_size)
{
    const float* x     = (const float*)d_in[0];
    const float* Wq    = (const float*)d_in[1];
    const float* bq    = (const float*)d_in[2];
    const float* Wk    = (const float*)d_in[3];
    const float* bk    = (const float*)d_in[4];
    const float* Wv    = (const float*)d_in[5];
    const float* bv    = (const float*)d_in[6];
    const float* gamma = (const float*)d_in[7];
    float* out = (float*)d_out;

    cudaFuncSetAttribute(proj_kernel, cudaFuncAttributeMaxDynamicSharedMemorySize,
                         SMEM_PROJ);
    cudaFuncSetAttribute(attn_kernel, cudaFuncAttributeMaxDynamicSharedMemorySize,
                         SMEM_ATTN);

    wconv_kernel<<<(CO * CH + 255) / 256, 256>>>(Wq, bq, Wk, bk, Wv, bv);

    dim3 gp(NSP / 128, BATCH, 2);      // (32, 4, 2) = 256 blocks, 2 CTAs/SM
    proj_kernel<<<gp, 256, SMEM_PROJ>>>(x);

    dim3 ga(NSP / TI, BATCH, NSPLIT);  // (64, 4, 4) = 1024 blocks, 3 CTAs/SM
    attn_kernel<<<ga, 128, SMEM_ATTN>>>();

    dim3 gc(NSP / 64, BATCH, 4);       // (64, 4, 4) = 1024 blocks
    combine_kernel<<<gc, 256>>>(x, gamma, out);
}

// round 17
// speedup vs baseline: 1.0341x; 1.0341x over previous
#include <cuda_runtime.h>
#include <cuda_fp16.h>
#include <cstdint>
#include <math.h>

#define BATCH 4
#define CH    128
#define C8    16
#define NSP   4096
#define CO    160
#define TI    64
#define TJ    64
#define NTJ   (NSP / TJ)
#define NSPLIT 4
#define NTJC  (NTJ / NSPLIT)   // 16 key-tiles per CTA

// f16 operands produced by proj kernel
__device__ __align__(16) __half g_q2[BATCH * NSP * 32];  // [b][n][ qh(16) | ql(16) ]
__device__ __align__(16) __half g_k2[BATCH * NSP * 32];  // [b][n][ kh(16) | kl(16) ]
__device__ __align__(16) __half g_v [BATCH * CH * NSP];  // [b][c][n] single f16

// split-K partials: per-split NORMALIZED O in f16, plus m/l in f32
__device__ __align__(16) __half g_po[NSPLIT * BATCH * CH * NSP];
__device__ float g_m[NSPLIT * BATCH * NSP];
__device__ float g_l[NSPLIT * BATCH * NSP];

extern __shared__ __align__(16) char dsmem[];

// ---------------------------------------------------------------------------
// helpers
// ---------------------------------------------------------------------------
__device__ __forceinline__ uint32_t smem_u32(const void* p) {
    uint32_t a;
    asm("{ .reg .u64 t; cvta.to.shared.u64 t, %1; cvt.u32.u64 %0, t; }"
        : "=r"(a) : "l"(p));
    return a;
}

#define LDSM4(r, addr) \
    asm volatile("ldmatrix.sync.aligned.m8n8.x4.shared.b16 {%0,%1,%2,%3}, [%4];" \
        : "=r"((r)[0]), "=r"((r)[1]), "=r"((r)[2]), "=r"((r)[3]) : "r"(addr))
#define LDSM4T(r, addr) \
    asm volatile("ldmatrix.sync.aligned.m8n8.x4.trans.shared.b16 {%0,%1,%2,%3}, [%4];" \
        : "=r"((r)[0]), "=r"((r)[1]), "=r"((r)[2]), "=r"((r)[3]) : "r"(addr))

// D(+=) = A(m16k16 f16) * B(k16n8 f16), f32 accum
#define MMAH(d, a, b) \
    asm volatile("mma.sync.aligned.m16n8k16.row.col.f32.f16.f16.f32 " \
        "{%0,%1,%2,%3}, {%4,%5,%6,%7}, {%8,%9}, {%0,%1,%2,%3};" \
        : "+f"((d)[0]), "+f"((d)[1]), "+f"((d)[2]), "+f"((d)[3]) \
        : "r"((a)[0]), "r"((a)[1]), "r"((a)[2]), "r"((a)[3]), \
          "r"((b)[0]), "r"((b)[1]))

#define CP16(dst, src) \
    asm volatile("cp.async.cg.shared.global [%0], [%1], 16;" :: "r"(dst), "l"(src))
#define CPCOMMIT() asm volatile("cp.async.commit_group;" ::: "memory")
#define CPWAIT0()  asm volatile("cp.async.wait_group 0;" ::: "memory")

#define LOG2E 1.4426950408889634f

// 2^t on the SFU pipe (MUFU.EX2)
__device__ __forceinline__ float fex2(float t) {
    float r;
    asm("ex2.approx.f32 %0, %1;" : "=f"(r) : "f"(t));
    return r;
}

__device__ __forceinline__ uint32_t packh2(float lo, float hi) {
    __half2 h = __floats2half2_rn(lo, hi);  // lo -> low 16 bits
    return *reinterpret_cast<uint32_t*>(&h);
}

// ---------------------------------------------------------------------------
// HMMA projection: O^T(n,160) = x^T(n,128) @ W^T(128,160) + b, f16 hi/lo.
// W is loaded as f32 and converted to f16 hi/lo in-kernel.
// Block = (128-n tile, batch), 256 threads. Grid (32,4) = one wave.
// ---------------------------------------------------------------------------
// smem byte offsets: x pitch 272B (136 f16), W pitch 272B
#define PJ_XH 0
#define PJ_XL 34816
#define PJ_WH 69632
#define PJ_WL 113152
#define PJ_BI 156672
#define SMEM_PROJ 157376

__global__ __launch_bounds__(256, 1) void proj_kernel(
    const float* __restrict__ x,
    const float* __restrict__ Wq, const float* __restrict__ bq,
    const float* __restrict__ Wk, const float* __restrict__ bk,
    const float* __restrict__ Wv, const float* __restrict__ bv)
{
    const uint32_t sb = smem_u32(dsmem);
    const int t    = threadIdx.x;
    const int lane = t & 31;
    const int w    = t >> 5;
    const int b    = blockIdx.y;
    const int n0   = blockIdx.x * 128;

    // W f32 -> f16 hi/lo smem [o][c], pitch 272 B. 160 rows x 32 float4.
    #pragma unroll
    for (int u = 0; u < 20; ++u) {
        int m = t + u * 256;
        int r = m >> 5, cq = m & 31;
        const float* src;
        if (r < 16)       src = Wq + r * CH;
        else if (r < 32)  src = Wk + (r - 16) * CH;
        else              src = Wv + (r - 32) * CH;
        float4 v = *(const float4*)(src + cq * 4);
        __half h0 = __float2half_rn(v.x), h1 = __float2half_rn(v.y);
        __half h2 = __float2half_rn(v.z), h3 = __float2half_rn(v.w);
        __half2 hp0; hp0.x = h0; hp0.y = h1;
        __half2 hp1; hp1.x = h2; hp1.y = h3;
        __half2 lp0; lp0.x = __float2half_rn(v.x - __half2float(h0));
        lp0.y = __float2half_rn(v.y - __half2float(h1));
        __half2 lp1; lp1.x = __float2half_rn(v.z - __half2float(h2));
        lp1.y = __float2half_rn(v.w - __half2float(h3));
        __half2* ph = (__half2*)(dsmem + PJ_WH + r * 272 + cq * 8);
        __half2* pl = (__half2*)(dsmem + PJ_WL + r * 272 + cq * 8);
        ph[0] = hp0; ph[1] = hp1;
        pl[0] = lp0; pl[1] = lp1;
    }
    // bias -> smem
    if (t < CO)
        ((float*)(dsmem + PJ_BI))[t] =
            (t < 16) ? bq[t] : (t < 32) ? bk[t - 16] : bv[t - 32];

    // x tile: 128c x 128n f32 -> f16 hi/lo smem [c][n], pitch 272 B
    const float* xb = x + (size_t)(b * CH) * NSP + n0;
    #pragma unroll
    for (int u = 0; u < 16; ++u) {
        int m  = t + u * 256;
        int c  = m >> 5, nq = m & 31;
        float4 v = *(const float4*)(xb + (size_t)c * NSP + nq * 4);
        __half h0 = __float2half_rn(v.x), h1 = __float2half_rn(v.y);
        __half h2 = __float2half_rn(v.z), h3 = __float2half_rn(v.w);
        __half l0 = __float2half_rn(v.x - __half2float(h0));
        __half l1 = __float2half_rn(v.y - __half2float(h1));
        __half l2 = __float2half_rn(v.z - __half2float(h2));
        __half l3 = __float2half_rn(v.w - __half2float(h3));
        __half2* ph = (__half2*)(dsmem + PJ_XH + c * 272 + nq * 8);
        __half2* pl = (__half2*)(dsmem + PJ_XL + c * 272 + nq * 8);
        __half2 a; a.x = h0; a.y = h1;
        __half2 bb; bb.x = h2; bb.y = h3;
        ph[0] = a; ph[1] = bb;
        a.x = l0; a.y = l1; bb.x = l2; bb.y = l3;
        pl[0] = a; pl[1] = bb;
    }
    __syncthreads();

    // ldmatrix address components
    const int krow = (lane & 7) + ((lane >> 4) << 3);
    const int mcol = ((lane >> 3) & 1) * 8;

    // A fragments of x^T (hi and lo), via ldmatrix.trans from [c][n] storage
    uint32_t Ah[8][4], Al[8][4];
    #pragma unroll
    for (int kt = 0; kt < 8; ++kt) {
        uint32_t addr = sb + PJ_XH + (uint32_t)(kt * 16 + krow) * 272
                        + (w * 16 + mcol) * 2;
        LDSM4T(Ah[kt], addr);
        LDSM4T(Al[kt], addr + (PJ_XL - PJ_XH));
    }

    float acc[20][4];
    #pragma unroll
    for (int a = 0; a < 20; ++a)
        #pragma unroll
        for (int d = 0; d < 4; ++d) acc[a][d] = 0.f;

    // O^T = xh@Wh + xl@Wh + xh@Wl
    #pragma unroll
    for (int ot = 0; ot < 10; ++ot) {
        #pragma unroll
        for (int kt = 0; kt < 8; ++kt) {
            uint32_t Bh[4], Bl[4];
            uint32_t ba = sb + PJ_WH + (uint32_t)(ot * 16 + krow) * 272
                          + (kt * 16 + mcol) * 2;
            LDSM4(Bh, ba);
            LDSM4(Bl, ba + (PJ_WL - PJ_WH));
            MMAH(acc[2 * ot],     Ah[kt], Bh);
            MMAH(acc[2 * ot + 1], Ah[kt], Bh + 2);
            MMAH(acc[2 * ot],     Al[kt], Bh);
            MMAH(acc[2 * ot + 1], Al[kt], Bh + 2);
            MMAH(acc[2 * ot],     Ah[kt], Bl);
            MMAH(acc[2 * ot + 1], Ah[kt], Bl + 2);
        }
    }

    // Epilogue: bias add, split outputs. ot=0 -> q, ot=1 -> k, ot>=2 -> v.
    const float* bias_s = (const float*)(dsmem + PJ_BI);
    const int gid = lane >> 2, m4 = lane & 3;
    const int na  = n0 + w * 16 + gid;

    #pragma unroll
    for (int ot = 0; ot < 10; ++ot) {
        #pragma unroll
        for (int h2 = 0; h2 < 2; ++h2) {
            const float* a = acc[2 * ot + h2];
            int o0 = ot * 16 + h2 * 8 + 2 * m4;
            float bb0 = bias_s[o0], bb1 = bias_s[o0 + 1];
            float v0 = a[0] + bb0, v1 = a[1] + bb1;
            float v2 = a[2] + bb0, v3 = a[3] + bb1;

            if (ot < 2) {
                __half* dst = (ot == 0) ? g_q2 : g_k2;
                int oc = o0 - ot * 16;
                size_t bA = ((size_t)b * NSP + na) * 32;
                size_t bB = ((size_t)b * NSP + na + 8) * 32;
                __half h;
                h = __float2half_rn(v0);
                dst[bA + oc]      = h;
                dst[bA + oc + 16] = __float2half_rn(v0 - __half2float(h));
                h = __float2half_rn(v1);
                dst[bA + oc + 1]  = h;
                dst[bA + oc + 17] = __float2half_rn(v1 - __half2float(h));
                h = __float2half_rn(v2);
                dst[bB + oc]      = h;
                dst[bB + oc + 16] = __float2half_rn(v2 - __half2float(h));
                h = __float2half_rn(v3);
                dst[bB + oc + 1]  = h;
                dst[bB + oc + 17] = __float2half_rn(v3 - __half2float(h));
            } else {
                int c = o0 - 32;
                size_t rb = ((size_t)b * CH + c) * NSP;
                g_v[rb + na]           = __float2half_rn(v0);
                g_v[rb + na + 8]       = __float2half_rn(v2);
                g_v[rb + NSP + na]     = __float2half_rn(v1);
                g_v[rb + NSP + na + 8] = __float2half_rn(v3);
            }
        }
    }
}

// ---------------------------------------------------------------------------
// HMMA flash attention, f16, online softmax, split-K over key tiles.
// 64-q CTA, 4 warps, 3 CTAs/SM; grid (64, 4, NSPLIT) = 1024 CTAs.
// Partials stored NORMALIZED in f16.
// ---------------------------------------------------------------------------
#define PI 68   // out staging pitch in f32

// smem byte offsets (per CTA: 52.7 KB -> 3 CTAs/SM)
#define OFF_Q    0
#define OFF_KS0  5120
#define OFF_V0   10240
#define OFF_KS1  28672
#define OFF_V1   33792
#define SMEM_ATTN (52224 + 512)

__device__ __forceinline__ void prefetch_tile(int b, int j0,
                                              uint32_t ks, uint32_t vs, int tid)
{
    // K: 64 rows x 64 B -> pitch 80 B
    {
        const char* kg = (const char*)(g_k2 + ((size_t)b * NSP + j0) * 32);
        #pragma unroll
        for (int u = 0; u < 2; ++u) {
            int m = tid + u * 128;
            int r = m >> 2, ch = m & 3;
            CP16(ks + (uint32_t)r * 80 + ch * 16, kg + (size_t)r * 64 + ch * 16);
        }
    }
    // V: 128 rows (c) x 128 B (64 f16 j) -> pitch 144 B
    const char* vg = (const char*)(g_v + (size_t)b * CH * NSP + j0);
    #pragma unroll
    for (int u = 0; u < 8; ++u) {
        int m = tid + u * 128;
        int r = m >> 3, ch = m & 7;
        CP16(vs + (uint32_t)r * 144 + ch * 16, vg + (size_t)r * (NSP * 2) + ch * 16);
    }
}

__global__ __launch_bounds__(128, 3) void attn_kernel()
{
    const uint32_t sb = smem_u32(dsmem);
    const int tid  = threadIdx.x;
    const int lane = tid & 31;
    const int wid  = tid >> 5;
    const int b    = blockIdx.y;
    const int h    = blockIdx.z;
    const int i0   = blockIdx.x * TI;
    const int iw   = wid * 16;
    const int gid  = lane >> 2;
    const int m4   = lane & 3;

    const uint32_t KS[2] = {sb + OFF_KS0, sb + OFF_KS1};
    const uint32_t VS[2] = {sb + OFF_V0,  sb + OFF_V1};
    float* outs = (float*)(dsmem + OFF_KS0);   // epilogue reuse

    // Load Q tile: 64 rows x 64 B -> pitch 80 B
    {
        const uint4* src = (const uint4*)(g_q2 + ((size_t)b * NSP + i0) * 32);
        #pragma unroll
        for (int u = 0; u < 2; ++u) {
            int m = tid + u * 128;
            int r = m >> 2, ch = m & 3;
            *(uint4*)(dsmem + OFF_Q + r * 80 + ch * 16) = src[m];
        }
    }
    prefetch_tile(b, h * NTJC * TJ, KS[0], VS[0], tid);
    CPCOMMIT();
    __syncthreads();

    // Resident A-fragments of Q (hi and lo)
    uint32_t qh[4], ql[4];
    {
        uint32_t a = sb + OFF_Q + (uint32_t)(iw + (lane & 15)) * 80 + (lane >> 4) * 16;
        LDSM4(qh, a);
        LDSM4(ql, a + 32);
    }

    // ldmatrix address components for B operands (non-trans)
    const int brow = (lane & 7) + ((lane >> 4) << 3);
    const int bcol = ((lane >> 3) & 1) * 8;

    float o[16][4];
    #pragma unroll
    for (int a = 0; a < 16; ++a)
        #pragma unroll
        for (int d = 0; d < 4; ++d) o[a][d] = 0.f;

    float lsum0 = 0.f, lsum1 = 0.f;
    float m0 = -60.f, m1 = -60.f;    // running row maxes (safe floor)

    for (int jt = 0; jt < NTJC; ++jt) {
        CPWAIT0();
        __syncthreads();
        if (jt + 1 < NTJC) {
            int ns = (jt + 1) & 1;
            prefetch_tile(b, (h * NTJC + jt + 1) * TJ, KS[ns], VS[ns], tid);
            CPCOMMIT();
        }
        const int st = jt & 1;

        // ---- QK: S(16i x 64j) = qh*kh + ql*kh + qh*kl  (kh frags reused)
        float sacc[8][4];
        #pragma unroll
        for (int a = 0; a < 8; ++a)
            #pragma unroll
            for (int d = 0; d < 4; ++d) sacc[a][d] = 0.f;

        #pragma unroll
        for (int np = 0; np < 4; ++np) {
            uint32_t base = KS[st] + (uint32_t)(16 * np + brow) * 80 + bcol * 2;
            uint32_t bKh[4], bKl[4];
            LDSM4(bKh, base);
            LDSM4(bKl, base + 32);
            MMAH(sacc[2 * np],     qh, bKh);
            MMAH(sacc[2 * np + 1], qh, bKh + 2);
            MMAH(sacc[2 * np],     ql, bKh);
            MMAH(sacc[2 * np + 1], ql, bKh + 2);
            MMAH(sacc[2 * np],     qh, bKl);
            MMAH(sacc[2 * np + 1], qh, bKl + 2);
        }

        // ---- online softmax: row max over this tile (rows live in lane quads)
        float tm0 = -1e30f, tm1 = -1e30f;
        #pragma unroll
        for (int a = 0; a < 8; ++a) {
            tm0 = fmaxf(tm0, fmaxf(sacc[a][0], sacc[a][1]));
            tm1 = fmaxf(tm1, fmaxf(sacc[a][2], sacc[a][3]));
        }
        tm0 = fmaxf(tm0, __shfl_xor_sync(0xFFFFFFFFu, tm0, 1));
        tm0 = fmaxf(tm0, __shfl_xor_sync(0xFFFFFFFFu, tm0, 2));
        tm1 = fmaxf(tm1, __shfl_xor_sync(0xFFFFFFFFu, tm1, 1));
        tm1 = fmaxf(tm1, __shfl_xor_sync(0xFFFFFFFFu, tm1, 2));

        const float mn0 = fmaxf(m0, tm0);
        const float mn1 = fmaxf(m1, tm1);
        const float sc0 = fex2((m0 - mn0) * LOG2E);
        const float sc1 = fex2((m1 - mn1) * LOG2E);
        m0 = mn0; m1 = mn1;
        lsum0 *= sc0;
        lsum1 *= sc1;
        // Rescale O only if some row max moved (rare after early tiles)
        if (__any_sync(0xFFFFFFFFu, (sc0 < 1.f) || (sc1 < 1.f))) {
            #pragma unroll
            for (int a = 0; a < 16; ++a) {
                o[a][0] *= sc0; o[a][1] *= sc0;
                o[a][2] *= sc1; o[a][3] *= sc1;
            }
        }

        // ---- p = exp(s - m) in (0,1] on the MUFU pipe; pack to f16 A-frags
        const float c0 = -mn0 * LOG2E;
        const float c1 = -mn1 * LOG2E;
        uint32_t ph[16];
        #pragma unroll
        for (int a = 0; a < 8; ++a) {
            float p0 = fex2(fmaf(sacc[a][0], LOG2E, c0));
            float p1 = fex2(fmaf(sacc[a][1], LOG2E, c0));
            float p2 = fex2(fmaf(sacc[a][2], LOG2E, c1));
            float p3 = fex2(fmaf(sacc[a][3], LOG2E, c1));
            lsum0 += p0 + p1;
            lsum1 += p2 + p3;
            ph[2 * a]     = packh2(p0, p1);
            ph[2 * a + 1] = packh2(p2, p3);
        }

        // ---- PV: O(16i x 128c) += P(f16) * V(f16)
        #pragma unroll
        for (int t4 = 0; t4 < 4; ++t4) {
            const uint32_t* A = &ph[4 * t4];
            #pragma unroll
            for (int p = 0; p < 8; ++p) {
                uint32_t bv[4];
                LDSM4(bv, VS[st] + (uint32_t)(16 * p + brow) * 144 + (16 * t4 + bcol) * 2);
                MMAH(o[2 * p],     A, bv);
                MMAH(o[2 * p + 1], A, bv + 2);
            }
        }
    }

    // ---- l reduction (4 lanes per row hold partials); write m/l partials
    lsum0 += __shfl_xor_sync(0xFFFFFFFFu, lsum0, 1);
    lsum0 += __shfl_xor_sync(0xFFFFFFFFu, lsum0, 2);
    lsum1 += __shfl_xor_sync(0xFFFFFFFFu, lsum1, 1);
    lsum1 += __shfl_xor_sync(0xFFFFFFFFu, lsum1, 2);
    if (m4 == 0) {
        size_t mb = ((size_t)h * BATCH + b) * NSP + i0 + iw;
        g_m[mb + gid]     = m0;
        g_m[mb + gid + 8] = m1;
        g_l[mb + gid]     = lsum0;
        g_l[mb + gid + 8] = lsum1;
    }
    __syncthreads();   // all PV reads of V/K smem complete before reuse

    // ---- stage per-split NORMALIZED O to smem [c][i]
    const float inv0 = 1.f / lsum0;
    const float inv1 = 1.f / lsum1;
    #pragma unroll
    for (int a = 0; a < 16; ++a) {
        int c = 8 * a + 2 * m4;
        outs[c * PI + iw + gid]           = o[a][0] * inv0;
        outs[(c + 1) * PI + iw + gid]     = o[a][1] * inv0;
        outs[c * PI + iw + gid + 8]       = o[a][2] * inv1;
        outs[(c + 1) * PI + iw + gid + 8] = o[a][3] * inv1;
    }
    __syncthreads();

    // ---- coalesced f16 partial-O store
    __half* pob = g_po + (((size_t)h * BATCH + b) * CH) * NSP + i0;
    for (int m = tid; m < CH * (TI / 4); m += 128) {
        int c = m >> 4, i4 = (m & 15) * 4;
        float4 ov = *(const float4*)(outs + c * PI + i4);
        uint2 hv;
        hv.x = packh2(ov.x, ov.y);
        hv.y = packh2(ov.z, ov.w);
        *(uint2*)(pob + (size_t)c * NSP + i4) = hv;
    }
}

// ---------------------------------------------------------------------------
// Combine: out = gamma * sum_h Ohat_h * (l_h a_h / sum l_h a_h) + x
// Vectorized: each thread handles an i-pair (half2 partial loads, float2 x/out)
// grid (32, 4, 8): i-tile 128, 16 channels per z-slice, 4 per thread group.
// ---------------------------------------------------------------------------
__global__ __launch_bounds__(256) void combine_kernel(
    const float* __restrict__ x,
    const float* __restrict__ gamma,
    float* __restrict__ out)
{
    const int t  = threadIdx.x;
    const int b  = blockIdx.y;
    const int u  = t & 63;                       // i-pair index
    const int i  = blockIdx.x * 128 + u * 2;
    const int cb = blockIdx.z * 16 + (t >> 6) * 4;  // 4 channels per group

    const size_t nidx = (size_t)b * NSP + i;
    float a0[NSPLIT], a1[NSPLIT];
    {
        float mh0[NSPLIT], mh1[NSPLIT], lh0[NSPLIT], lh1[NSPLIT];
        float M0 = -1e30f, M1 = -1e30f;
        #pragma unroll
        for (int h = 0; h < NSPLIT; ++h) {
            size_t o = (size_t)h * BATCH * NSP + nidx;
            mh0[h] = g_m[o];     mh1[h] = g_m[o + 1];
            lh0[h] = g_l[o];     lh1[h] = g_l[o + 1];
            M0 = fmaxf(M0, mh0[h]);
            M1 = fmaxf(M1, mh1[h]);
        }
        float d0 = 0.f, d1 = 0.f;
        #pragma unroll
        for (int h = 0; h < NSPLIT; ++h) {
            a0[h] = lh0[h] * fex2((mh0[h] - M0) * LOG2E);
            a1[h] = lh1[h] * fex2((mh1[h] - M1) * LOG2E);
            d0 += a0[h];
            d1 += a1[h];
        }
        const float g  = gamma[0];
        const float g0 = g / d0, g1 = g / d1;
        #pragma unroll
        for (int h = 0; h < NSPLIT; ++h) { a0[h] *= g0; a1[h] *= g1; }
    }

    #pragma unroll
    for (int cc = 0; cc < 4; ++cc) {
        int c = cb + cc;
        size_t off = ((size_t)b * CH + c) * NSP + i;
        float2 xv = *(const float2*)(x + off);
        float acc0 = xv.x, acc1 = xv.y;
        #pragma unroll
        for (int h = 0; h < NSPLIT; ++h) {
            __half2 p2 = *(const __half2*)(g_po + (size_t)h * BATCH * CH * NSP + off);
            float2 pf = __half22float2(p2);
            acc0 = fmaf(pf.x, a0[h], acc0);
            acc1 = fmaf(pf.y, a1[h], acc1);
        }
        float2 ov; ov.x = acc0; ov.y = acc1;
        *(float2*)(out + off) = ov;
    }
}

// ---------------------------------------------------------------------------
extern "C" void kernel_launch(void* const* d_in, const int* in_sizes, int n_in,
                              void* d_out, int out_size)
{
    const float* x     = (const float*)d_in[0];
    const float* Wq    = (const float*)d_in[1];
    const float* bq    = (const float*)d_in[2];
    const float* Wk    = (const float*)d_in[3];
    const float* bk    = (const float*)d_in[4];
    const float* Wv    = (const float*)d_in[5];
    const float* bv    = (const float*)d_in[6];
    const float* gamma = (const float*)d_in[7];
    float* out = (float*)d_out;

    cudaFuncSetAttribute(proj_kernel, cudaFuncAttributeMaxDynamicSharedMemorySize,
                         SMEM_PROJ);
    cudaFuncSetAttribute(attn_kernel, cudaFuncAttributeMaxDynamicSharedMemorySize,
                         SMEM_ATTN);

    dim3 gp(NSP / 128, BATCH);         // (32, 4) = 128 blocks, single wave
    proj_kernel<<<gp, 256, SMEM_PROJ>>>(x, Wq, bq, Wk, bk, Wv, bv);

    dim3 ga(NSP / TI, BATCH, NSPLIT);  // (64, 4, 4) = 1024 blocks, 3 CTAs/SM
    attn_kernel<<<ga, 128, SMEM_ATTN>>>();

    dim3 gc(NSP / 128, BATCH, 8);      // (32, 4, 8) = 1024 blocks
    combine_kernel<<<gc, 256>>>(x, gamma, out);
}